// round 12
// baseline (speedup 1.0000x reference)
#include <cuda_runtime.h>
#include <cuda_fp16.h>

#define BB 8
#define NN 2048
#define DD 256
#define KK 8192
#define M_TOK (BB*NN)          // 16384

#define M_TILE 64
#define N_TILE 128
#define NT (KK / N_TILE)       // 64 n-tiles
#define NCHUNK (NT * 4)        // 256 chunks of 64 halves (4 per n-tile)
#define THREADS 256
#define EPS 0.25f

#define LDA 264                // A smem stride in halves (528 B, conflict-free ldmatrix)
#define LDB_BYTES 144          // B smem row stride in bytes (64 halves + 16B pad)
#define B_STAGE 18432          // 128 * 144

// smem byte offsets (per-CTA total 70656 -> 2 CTAs/SM)
#define SM_AHI 0
#define SM_B   33792                    // 64*264*2 ; 2 stages x 18432
#define SMEM_TOTAL 70656

__device__ __align__(1024) __half g_cb_hi[KK*DD];
__device__ float g_c2[KK];
__device__ int   g_idx[M_TOK];
__device__ int   g_flag[M_TOK];
__device__ int   g_list[M_TOK];
__device__ int   g_nflag;
__device__ unsigned long long g_resc[M_TOK];

// ---- PTX helpers -----------------------------------------------------------
__device__ __forceinline__ void ldsm4(unsigned& r0, unsigned& r1, unsigned& r2,
                                      unsigned& r3, unsigned addr) {
    asm volatile("ldmatrix.sync.aligned.m8n8.x4.shared.b16 {%0,%1,%2,%3}, [%4];"
                 : "=r"(r0), "=r"(r1), "=r"(r2), "=r"(r3) : "r"(addr));
}
__device__ __forceinline__ void mma16816(float* c, unsigned a0, unsigned a1,
                                         unsigned a2, unsigned a3,
                                         unsigned b0, unsigned b1) {
    asm volatile("mma.sync.aligned.m16n8k16.row.col.f32.f16.f16.f32 "
                 "{%0,%1,%2,%3}, {%4,%5,%6,%7}, {%8,%9}, {%0,%1,%2,%3};"
                 : "+f"(c[0]), "+f"(c[1]), "+f"(c[2]), "+f"(c[3])
                 : "r"(a0), "r"(a1), "r"(a2), "r"(a3), "r"(b0), "r"(b1));
}
__device__ __forceinline__ void cp16(unsigned dst, const void* src) {
    asm volatile("cp.async.cg.shared.global [%0], [%1], 16;"
                 :: "r"(dst), "l"((unsigned long long)__cvta_generic_to_global(src))
                 : "memory");
}
#define CP_COMMIT() asm volatile("cp.async.commit_group;" ::: "memory")
#define CP_WAIT1()  asm volatile("cp.async.wait_group 1;" ::: "memory")

__device__ __forceinline__ unsigned long long u64min(unsigned long long a,
                                                     unsigned long long b) {
    return a < b ? a : b;
}

// ---------------------------------------------------------------------------
// Kernel 1: codebook fp16 hi split + squared norms. One block per code row.
// ---------------------------------------------------------------------------
__global__ void cvt_cb_kernel(const float* __restrict__ cb) {
    const int row = blockIdx.x, d = threadIdx.x;
    if (row == 0 && d == 0) g_nflag = 0;            // reset flag counter each launch
    float v = cb[row * DD + d];
    g_cb_hi[row * DD + d] = __float2half_rn(v);
    float s = v * v;
    #pragma unroll
    for (int o = 16; o; o >>= 1) s += __shfl_xor_sync(0xffffffffu, s, o);
    __shared__ float ws[8];
    if ((threadIdx.x & 31) == 0) ws[threadIdx.x >> 5] = s;
    __syncthreads();
    if (threadIdx.x == 0) {
        float t = 0.f;
        #pragma unroll
        for (int w = 0; w < 8; w++) t += ws[w];
        g_c2[row] = t;
    }
}

// ---------------------------------------------------------------------------
// Kernel 2: single-pass fp16-hi HMMA + top-2 argmin + tie flagging
// ---------------------------------------------------------------------------
__global__ void __launch_bounds__(THREADS, 2)
vq_mma_kernel(const float* __restrict__ x) {
    extern __shared__ char smem[];
    const unsigned sb = (unsigned)__cvta_generic_to_shared(smem);
    const int tid  = threadIdx.x;
    const int wid  = tid >> 5;
    const int lane = tid & 31;
    const int wm   = wid >> 2;          // 0..1  (32 rows each)
    const int wn   = wid & 3;           // 0..3  (32 cols each)
    const int rowBase = blockIdx.x * M_TILE;

    // ---- load A tile: 64 tokens x 256 d, fp32 -> fp16 hi in padded smem
    for (int r = 0; r < 16; r++) {
        int i   = r * THREADS + tid;         // float4 index, 4096 total
        int tok = i >> 6, dg = i & 63;
        float4 v = __ldg((const float4*)(x + (size_t)(rowBase + tok) * DD + dg * 4));
        unsigned off = (unsigned)(tok * LDA + dg * 4) * 2;
        *(__half2*)(smem + SM_AHI + off)     = __halves2half2(__float2half_rn(v.x),
                                                              __float2half_rn(v.y));
        *(__half2*)(smem + SM_AHI + off + 4) = __halves2half2(__float2half_rn(v.z),
                                                              __float2half_rn(v.w));
    }
    __syncthreads();

    // per-thread ldmatrix base offsets
    const unsigned aoff = ((unsigned)((wm * 32 + (lane & 15)) * LDA) + (lane >> 4) * 8) * 2;
    const unsigned boff = (unsigned)(wn * 32 + (lane >> 4) * 8 + (lane & 7)) * LDB_BYTES
                        + (unsigned)((lane >> 3) & 1) * 16;

    float acc[2][4][4];
    #pragma unroll
    for (int mi = 0; mi < 2; mi++)
        #pragma unroll
        for (int ni = 0; ni < 4; ni++)
            #pragma unroll
            for (int q = 0; q < 4; q++) acc[mi][ni][q] = 0.f;

    float b1[2][2], b2[2][2];
    int   i1[2][2];
    #pragma unroll
    for (int mi = 0; mi < 2; mi++)
        #pragma unroll
        for (int rr = 0; rr < 2; rr++) {
            b1[mi][rr] = 3.4e38f; b2[mi][rr] = 3.4e38f; i1[mi][rr] = 0;
        }

    // prefetch chunk 0 into stage 0  (chunk = 128 codes x 64 halves, hi only)
    #pragma unroll
    for (int rep = 0; rep < 4; rep++) {
        int idx = rep * THREADS + tid;               // 1024 x 16B
        int r = idx >> 3, cc = idx & 7;
        cp16(sb + SM_B + r * LDB_BYTES + cc * 16,
             g_cb_hi + ((size_t)r * DD + cc * 8));
    }
    CP_COMMIT();

    for (int g = 0; g < NCHUNK; g++) {
        if (g + 1 < NCHUNK) {
            const int nt = (g + 1) >> 2, kc4 = (g + 1) & 3, st = (g + 1) & 1;
            #pragma unroll
            for (int rep = 0; rep < 4; rep++) {
                int idx = rep * THREADS + tid;
                int r = idx >> 3, cc = idx & 7;
                cp16(sb + SM_B + st * B_STAGE + r * LDB_BYTES + cc * 16,
                     g_cb_hi + ((size_t)(nt * N_TILE + r) * DD + kc4 * 64 + cc * 8));
            }
        }
        CP_COMMIT();
        CP_WAIT1();
        __syncthreads();

        const unsigned bbase = sb + SM_B + (unsigned)(g & 1) * B_STAGE;
        const unsigned kb2 = (unsigned)(g & 3) * 128;         // A byte offset of this chunk

        #pragma unroll
        for (int k16 = 0; k16 < 4; k16++) {
            const unsigned kaA = kb2 + (unsigned)k16 * 32;    // A: full-K resident
            const unsigned kaB = (unsigned)k16 * 32;          // B: chunk-relative
            unsigned ah[2][4], bh[2][4];
            #pragma unroll
            for (int mi = 0; mi < 2; mi++)
                ldsm4(ah[mi][0], ah[mi][1], ah[mi][2], ah[mi][3],
                      sb + SM_AHI + aoff + (unsigned)(mi * 16 * LDA * 2) + kaA);
            #pragma unroll
            for (int p = 0; p < 2; p++)
                ldsm4(bh[p][0], bh[p][1], bh[p][2], bh[p][3],
                      bbase + boff + (unsigned)(p * 16 * LDB_BYTES) + kaB);
            #pragma unroll
            for (int mi = 0; mi < 2; mi++)
                #pragma unroll
                for (int ni = 0; ni < 4; ni++)
                    mma16816(acc[mi][ni], ah[mi][0], ah[mi][1], ah[mi][2], ah[mi][3],
                             bh[ni >> 1][(ni & 1) * 2], bh[ni >> 1][(ni & 1) * 2 + 1]);
        }

        if ((g & 3) == 3) {
            // drain: s = c2 - 2*cross, track top-2; zero accumulators
            const int nt = g >> 2;
            #pragma unroll
            for (int ni = 0; ni < 4; ni++) {
                int col = nt * N_TILE + wn * 32 + ni * 8 + (lane & 3) * 2;
                float c20 = __ldg(&g_c2[col]);
                float c21 = __ldg(&g_c2[col + 1]);
                #pragma unroll
                for (int mi = 0; mi < 2; mi++) {
                    #pragma unroll
                    for (int rr = 0; rr < 2; rr++) {
                        float s0 = fmaf(-2.0f, acc[mi][ni][rr * 2],     c20);
                        float s1 = fmaf(-2.0f, acc[mi][ni][rr * 2 + 1], c21);
                        if (s0 < b1[mi][rr]) { b2[mi][rr] = b1[mi][rr]; b1[mi][rr] = s0; i1[mi][rr] = col; }
                        else if (s0 < b2[mi][rr]) b2[mi][rr] = s0;
                        if (s1 < b1[mi][rr]) { b2[mi][rr] = b1[mi][rr]; b1[mi][rr] = s1; i1[mi][rr] = col + 1; }
                        else if (s1 < b2[mi][rr]) b2[mi][rr] = s1;
                        acc[mi][ni][rr * 2]     = 0.f;
                        acc[mi][ni][rr * 2 + 1] = 0.f;
                    }
                }
            }
        }
        __syncthreads();   // protect stage g&1 before next prefetch overwrites it
    }

    // ---- cross-thread top-2 merge (16 candidates per row), reuse B region
    float* rv1 = (float*)(smem + SM_B);             // [64][16]
    int*   ri1 = (int*)  (smem + SM_B + 4096);
    float* rv2 = (float*)(smem + SM_B + 8192);
    const int cand = wn * 4 + (lane & 3);
    #pragma unroll
    for (int mi = 0; mi < 2; mi++)
        #pragma unroll
        for (int rr = 0; rr < 2; rr++) {
            int row = wm * 32 + mi * 16 + rr * 8 + (lane >> 2);
            rv1[row * 16 + cand] = b1[mi][rr];
            ri1[row * 16 + cand] = i1[mi][rr];
            rv2[row * 16 + cand] = b2[mi][rr];
        }
    __syncthreads();
    if (tid < M_TILE) {
        float bv1 = rv1[tid * 16];
        int   bi  = ri1[tid * 16];
        float bv2 = rv2[tid * 16];
        #pragma unroll
        for (int t = 1; t < 16; t++) {
            float v1 = rv1[tid * 16 + t];
            int   ii = ri1[tid * 16 + t];
            float v2 = rv2[tid * 16 + t];
            if (v1 < bv1) { bv2 = fminf(bv1, v2); bv1 = v1; bi = ii; }
            else { if (v1 == bv1 && ii < bi) bi = ii; bv2 = fminf(bv2, v1); }
        }
        const int tok = rowBase + tid;
        g_idx[tok] = bi;
        int fl = (bv2 - bv1 < EPS) ? 1 : 0;
        g_flag[tok] = fl;
        if (fl) {
            g_resc[tok] = ~0ull;
            int p = atomicAdd(&g_nflag, 1);
            g_list[p] = tok;
        }
    }
}

// ---------------------------------------------------------------------------
// Kernel 3: exact fp32 rescore of flagged tokens.
//   grid = 512: 128 code tiles (64 codes) x 4 token groups. Code tile cached
//   in smem once per block; packed (dist,idx) atomicMin = exact first-min.
// ---------------------------------------------------------------------------
#define RS_SMEM (64 * 260 * 4 + 256 * 4)
__global__ void __launch_bounds__(256, 2)
resc_kernel(const float* __restrict__ x, const float* __restrict__ cb) {
    extern __shared__ float rs[];
    float* cs = rs;                  // [64][260] padded (conflict-free)
    float* xs = rs + 64 * 260;       // [256]
    __shared__ unsigned long long wmin[8];
    const int tid = threadIdx.x;
    const int ct  = blockIdx.x & 127;     // code tile: 64 codes
    const int tg  = blockIdx.x >> 7;      // 0..3

    for (int i = tid; i < 64 * 64; i += 256) {     // 4096 float4
        int j = i >> 6, dg = i & 63;
        float4 v = __ldg((const float4*)(cb + (size_t)(ct * 64 + j) * DD + dg * 4));
        *(float4*)(cs + j * 260 + dg * 4) = v;
    }
    __syncthreads();

    const int nf = g_nflag;
    const int j = tid >> 2, q = tid & 3;
    const float c2v = __ldg(&g_c2[ct * 64 + j]);

    for (int li = tg; li < nf; li += 4) {
        const int tok = g_list[li];
        xs[tid] = __ldg(x + (size_t)tok * DD + tid);
        __syncthreads();
        float p = 0.f;
        const float* xr = xs + q * 64;
        const float* cr = cs + j * 260 + q * 64;
        #pragma unroll
        for (int d = 0; d < 64; d += 4) {
            float4 xv = *(const float4*)(xr + d);
            float4 cv = *(const float4*)(cr + d);
            p += xv.x * cv.x + xv.y * cv.y + xv.z * cv.z + xv.w * cv.w;
        }
        p += __shfl_xor_sync(0xffffffffu, p, 1);
        p += __shfl_xor_sync(0xffffffffu, p, 2);
        unsigned long long key = ~0ull;
        if (q == 0) {
            float s = c2v - 2.f * p + 4096.f;     // shift keeps s > 0 -> monotone bits
            key = ((unsigned long long)__float_as_uint(s) << 32)
                | (unsigned)(ct * 64 + j);
        }
        key = u64min(key, __shfl_xor_sync(0xffffffffu, key, 4));
        key = u64min(key, __shfl_xor_sync(0xffffffffu, key, 8));
        key = u64min(key, __shfl_xor_sync(0xffffffffu, key, 16));
        if ((tid & 31) == 0) wmin[tid >> 5] = key;
        __syncthreads();
        if (tid == 0) {
            unsigned long long k = wmin[0];
            #pragma unroll
            for (int w = 1; w < 8; w++) k = u64min(k, wmin[w]);
            atomicMin(&g_resc[tok], k);
        }
        __syncthreads();
    }
}

// ---------------------------------------------------------------------------
// Kernel 4: outputs. Layout: [x_recon | z_e | z_q | indices(float)]
// ---------------------------------------------------------------------------
__global__ void scatter_kernel(const float* __restrict__ x,
                               const float* __restrict__ cb,
                               float* __restrict__ out) {
    const int t = blockIdx.x;
    const int d = threadIdx.x;
    const int idx = g_flag[t] ? (int)(unsigned)(g_resc[t] & 0xffffffffull) : g_idx[t];
    const float v  = __ldg(cb + (size_t)idx * DD + d);
    const float xe = __ldg(x  + (size_t)t   * DD + d);
    const size_t BND = (size_t)M_TOK * DD;
    out[(size_t)t * DD + d]           = v;
    out[BND + (size_t)t * DD + d]     = xe;
    out[2 * BND + (size_t)t * DD + d] = v;
    if (d == 0) out[3 * BND + t] = (float)idx;
}

// ---------------------------------------------------------------------------
extern "C" void kernel_launch(void* const* d_in, const int* in_sizes, int n_in,
                              void* d_out, int out_size) {
    const float* x  = (const float*)d_in[0];
    const float* cb = (const float*)d_in[1];
    float* out = (float*)d_out;

    cvt_cb_kernel<<<KK, DD>>>(cb);

    cudaFuncSetAttribute(vq_mma_kernel,
                         cudaFuncAttributeMaxDynamicSharedMemorySize, SMEM_TOTAL);
    vq_mma_kernel<<<M_TOK / M_TILE, THREADS, SMEM_TOTAL>>>(x);

    cudaFuncSetAttribute(resc_kernel,
                         cudaFuncAttributeMaxDynamicSharedMemorySize, RS_SMEM);
    resc_kernel<<<512, 256, RS_SMEM>>>(x, cb);

    scatter_kernel<<<M_TOK, DD>>>(x, cb, out);
}

// round 13
// speedup vs baseline: 2.3303x; 2.3303x over previous
#include <cuda_runtime.h>
#include <cuda_fp16.h>

#define BB 8
#define NN 2048
#define DD 256
#define KK 8192
#define M_TOK (BB*NN)          // 16384

#define M_TILE 64
#define N_TILE 128
#define NT (KK / N_TILE)       // 64 n-tiles
#define NCHUNK (NT * 8)        // 512 chunks of 32 halves (8 per n-tile) - R10 skeleton
#define THREADS 256
#define EPS 0.25f

#define LDA 264                // A smem stride in halves (528 B, conflict-free ldmatrix)
#define LDB 40                 // B smem stride in halves (80 B) - R10 proven
#define B_STAGE 10240          // 128 * 80 (hi only)

// smem byte offsets
#define SM_AHI 0
#define SM_B   33792                    // 64*264*2 ; 2 stages x 10240
#define SMEM_TOTAL 54272

__device__ __align__(1024) __half g_cb_hi[KK*DD];
__device__ float g_c2[KK];
__device__ int   g_idx[M_TOK];
__device__ int   g_flag[M_TOK];
__device__ int   g_list[M_TOK];
__device__ int   g_nflag;
__device__ unsigned long long g_resc[M_TOK];

// ---- PTX helpers -----------------------------------------------------------
__device__ __forceinline__ void ldsm4(unsigned& r0, unsigned& r1, unsigned& r2,
                                      unsigned& r3, unsigned addr) {
    asm volatile("ldmatrix.sync.aligned.m8n8.x4.shared.b16 {%0,%1,%2,%3}, [%4];"
                 : "=r"(r0), "=r"(r1), "=r"(r2), "=r"(r3) : "r"(addr));
}
__device__ __forceinline__ void mma16816(float* c, unsigned a0, unsigned a1,
                                         unsigned a2, unsigned a3,
                                         unsigned b0, unsigned b1) {
    asm volatile("mma.sync.aligned.m16n8k16.row.col.f32.f16.f16.f32 "
                 "{%0,%1,%2,%3}, {%4,%5,%6,%7}, {%8,%9}, {%0,%1,%2,%3};"
                 : "+f"(c[0]), "+f"(c[1]), "+f"(c[2]), "+f"(c[3])
                 : "r"(a0), "r"(a1), "r"(a2), "r"(a3), "r"(b0), "r"(b1));
}
__device__ __forceinline__ void cp16(unsigned dst, const void* src) {
    asm volatile("cp.async.cg.shared.global [%0], [%1], 16;"
                 :: "r"(dst), "l"((unsigned long long)__cvta_generic_to_global(src))
                 : "memory");
}
#define CP_COMMIT() asm volatile("cp.async.commit_group;" ::: "memory")
#define CP_WAIT1()  asm volatile("cp.async.wait_group 1;" ::: "memory")

__device__ __forceinline__ unsigned long long u64min(unsigned long long a,
                                                     unsigned long long b) {
    return a < b ? a : b;
}

// ---------------------------------------------------------------------------
// Kernel 1: codebook fp16 hi split + squared norms. One block per code row.
// ---------------------------------------------------------------------------
__global__ void cvt_cb_kernel(const float* __restrict__ cb) {
    const int row = blockIdx.x, d = threadIdx.x;
    if (row == 0 && d == 0) g_nflag = 0;            // reset flag counter each launch
    float v = cb[row * DD + d];
    g_cb_hi[row * DD + d] = __float2half_rn(v);
    float s = v * v;
    #pragma unroll
    for (int o = 16; o; o >>= 1) s += __shfl_xor_sync(0xffffffffu, s, o);
    __shared__ float ws[8];
    if ((threadIdx.x & 31) == 0) ws[threadIdx.x >> 5] = s;
    __syncthreads();
    if (threadIdx.x == 0) {
        float t = 0.f;
        #pragma unroll
        for (int w = 0; w < 8; w++) t += ws[w];
        g_c2[row] = t;
    }
}

// ---------------------------------------------------------------------------
// Kernel 2: single-pass fp16-hi HMMA + top-2 argmin + tie flagging
//   (R10-proven mainloop skeleton, lo pass removed)
// ---------------------------------------------------------------------------
__global__ void __launch_bounds__(THREADS, 2)
vq_mma_kernel(const float* __restrict__ x) {
    extern __shared__ char smem[];
    const unsigned sb = (unsigned)__cvta_generic_to_shared(smem);
    const int tid  = threadIdx.x;
    const int wid  = tid >> 5;
    const int lane = tid & 31;
    const int wm   = wid >> 2;          // 0..1  (32 rows each)
    const int wn   = wid & 3;           // 0..3  (32 cols each)
    const int rowBase = blockIdx.x * M_TILE;

    // ---- load A tile: 64 tokens x 256 d, fp32 -> fp16 hi in padded smem
    for (int r = 0; r < 16; r++) {
        int i   = r * THREADS + tid;         // float4 index, 4096 total
        int tok = i >> 6, dg = i & 63;
        float4 v = __ldg((const float4*)(x + (size_t)(rowBase + tok) * DD + dg * 4));
        unsigned off = (unsigned)(tok * LDA + dg * 4) * 2;
        *(__half2*)(smem + SM_AHI + off)     = __halves2half2(__float2half_rn(v.x),
                                                              __float2half_rn(v.y));
        *(__half2*)(smem + SM_AHI + off + 4) = __halves2half2(__float2half_rn(v.z),
                                                              __float2half_rn(v.w));
    }
    __syncthreads();

    // per-thread ldmatrix base offsets
    const unsigned aoff = ((unsigned)((wm * 32 + (lane & 15)) * LDA) + (lane >> 4) * 8) * 2;
    const unsigned boff = ((unsigned)((wn * 32 + (lane >> 4) * 8 + (lane & 7)) * LDB)
                           + ((lane >> 3) & 1) * 8) * 2;

    float acc[2][4][4];
    #pragma unroll
    for (int mi = 0; mi < 2; mi++)
        #pragma unroll
        for (int ni = 0; ni < 4; ni++)
            #pragma unroll
            for (int q = 0; q < 4; q++) acc[mi][ni][q] = 0.f;

    float b1[2][2], b2[2][2];
    int   i1[2][2];
    #pragma unroll
    for (int mi = 0; mi < 2; mi++)
        #pragma unroll
        for (int rr = 0; rr < 2; rr++) {
            b1[mi][rr] = 3.4e38f; b2[mi][rr] = 3.4e38f; i1[mi][rr] = 0;
        }

    // prefetch chunk 0 into stage 0  (chunk = 128 codes x 32 halves, hi only)
    #pragma unroll
    for (int rep = 0; rep < 2; rep++) {
        int idx = rep * THREADS + tid;               // 512 x 16B
        int r = idx >> 2, cc = idx & 3;
        cp16(sb + SM_B + r * (LDB * 2) + cc * 16,
             g_cb_hi + ((size_t)r * DD + cc * 8));
    }
    CP_COMMIT();

    for (int g = 0; g < NCHUNK; g++) {
        // prefetch chunk g+1 into stage (g+1)&1
        if (g + 1 < NCHUNK) {
            const int nt = (g + 1) >> 3, kc = (g + 1) & 7, st = (g + 1) & 1;
            #pragma unroll
            for (int rep = 0; rep < 2; rep++) {
                int idx = rep * THREADS + tid;
                int r = idx >> 2, cc = idx & 3;
                cp16(sb + SM_B + st * B_STAGE + r * (LDB * 2) + cc * 16,
                     g_cb_hi + ((size_t)(nt * N_TILE + r) * DD + kc * 32 + cc * 8));
            }
        }
        CP_COMMIT();
        CP_WAIT1();
        __syncthreads();

        const unsigned bbase = sb + SM_B + (unsigned)(g & 1) * B_STAGE;
        const unsigned kb2 = (unsigned)((g & 7) * 32) * 2;    // A k-chunk byte offset

        #pragma unroll
        for (int k16 = 0; k16 < 2; k16++) {
            const unsigned kaA = kb2 + (unsigned)k16 * 32;    // A: full-K resident
            const unsigned kaB = (unsigned)k16 * 32;          // B: stage chunk-relative
            unsigned ah[2][4], bh[2][4];
            #pragma unroll
            for (int mi = 0; mi < 2; mi++)
                ldsm4(ah[mi][0], ah[mi][1], ah[mi][2], ah[mi][3],
                      sb + SM_AHI + aoff + (unsigned)(mi * 16 * LDA * 2) + kaA);
            #pragma unroll
            for (int p = 0; p < 2; p++)
                ldsm4(bh[p][0], bh[p][1], bh[p][2], bh[p][3],
                      bbase + boff + (unsigned)(p * 16 * LDB * 2) + kaB);
            #pragma unroll
            for (int mi = 0; mi < 2; mi++)
                #pragma unroll
                for (int ni = 0; ni < 4; ni++)
                    mma16816(acc[mi][ni], ah[mi][0], ah[mi][1], ah[mi][2], ah[mi][3],
                             bh[ni >> 1][(ni & 1) * 2], bh[ni >> 1][(ni & 1) * 2 + 1]);
        }

        if ((g & 7) == 7) {
            // drain: s = c2 - 2*cross, track top-2; zero accumulators
            const int nt = g >> 3;
            #pragma unroll
            for (int ni = 0; ni < 4; ni++) {
                int col = nt * N_TILE + wn * 32 + ni * 8 + (lane & 3) * 2;
                float c20 = __ldg(&g_c2[col]);
                float c21 = __ldg(&g_c2[col + 1]);
                #pragma unroll
                for (int mi = 0; mi < 2; mi++) {
                    #pragma unroll
                    for (int rr = 0; rr < 2; rr++) {
                        float s0 = fmaf(-2.0f, acc[mi][ni][rr * 2],     c20);
                        float s1 = fmaf(-2.0f, acc[mi][ni][rr * 2 + 1], c21);
                        if (s0 < b1[mi][rr]) { b2[mi][rr] = b1[mi][rr]; b1[mi][rr] = s0; i1[mi][rr] = col; }
                        else if (s0 < b2[mi][rr]) b2[mi][rr] = s0;
                        if (s1 < b1[mi][rr]) { b2[mi][rr] = b1[mi][rr]; b1[mi][rr] = s1; i1[mi][rr] = col + 1; }
                        else if (s1 < b2[mi][rr]) b2[mi][rr] = s1;
                        acc[mi][ni][rr * 2]     = 0.f;
                        acc[mi][ni][rr * 2 + 1] = 0.f;
                    }
                }
            }
        }
        __syncthreads();   // protect stage g&1 before next prefetch overwrites it
    }

    // ---- cross-thread top-2 merge (16 candidates per row), reuse B region
    float* rv1 = (float*)(smem + SM_B);             // [64][16]
    int*   ri1 = (int*)  (smem + SM_B + 4096);
    float* rv2 = (float*)(smem + SM_B + 8192);
    const int cand = wn * 4 + (lane & 3);
    #pragma unroll
    for (int mi = 0; mi < 2; mi++)
        #pragma unroll
        for (int rr = 0; rr < 2; rr++) {
            int row = wm * 32 + mi * 16 + rr * 8 + (lane >> 2);
            rv1[row * 16 + cand] = b1[mi][rr];
            ri1[row * 16 + cand] = i1[mi][rr];
            rv2[row * 16 + cand] = b2[mi][rr];
        }
    __syncthreads();
    if (tid < M_TILE) {
        float bv1 = rv1[tid * 16];
        int   bi  = ri1[tid * 16];
        float bv2 = rv2[tid * 16];
        #pragma unroll
        for (int t = 1; t < 16; t++) {
            float v1 = rv1[tid * 16 + t];
            int   ii = ri1[tid * 16 + t];
            float v2 = rv2[tid * 16 + t];
            if (v1 < bv1) { bv2 = fminf(bv1, v2); bv1 = v1; bi = ii; }
            else { if (v1 == bv1 && ii < bi) bi = ii; bv2 = fminf(bv2, v1); }
        }
        const int tok = rowBase + tid;
        g_idx[tok] = bi;
        int fl = (bv2 - bv1 < EPS) ? 1 : 0;
        g_flag[tok] = fl;
        if (fl) {
            g_resc[tok] = ~0ull;
            int p = atomicAdd(&g_nflag, 1);
            g_list[p] = tok;
        }
    }
}

// ---------------------------------------------------------------------------
// Kernel 3: exact fp32 rescore of flagged tokens (v2: code tile in registers).
//   grid = 512: 128 code tiles (64 codes) x 4 token groups.
//   Thread (j=tid>>2, q=tid&3) owns 64 floats of code ct*64+j.
// ---------------------------------------------------------------------------
__global__ void __launch_bounds__(256, 2)
resc_kernel(const float* __restrict__ x, const float* __restrict__ cb) {
    __shared__ float xs[256];
    __shared__ unsigned long long wmin[8];
    const int tid = threadIdx.x;
    const int ct  = blockIdx.x & 127;     // code tile: 64 codes
    const int tg  = blockIdx.x >> 7;      // 0..3
    const int j = tid >> 2, q = tid & 3;
    const int code = ct * 64 + j;

    const int nf = g_nflag;
    if (nf == 0) return;

    float creg[64];
    {
        const float4* csrc = (const float4*)(cb + (size_t)code * DD + q * 64);
        #pragma unroll
        for (int d4 = 0; d4 < 16; d4++) {
            float4 v = __ldg(csrc + d4);
            creg[d4 * 4]     = v.x; creg[d4 * 4 + 1] = v.y;
            creg[d4 * 4 + 2] = v.z; creg[d4 * 4 + 3] = v.w;
        }
    }
    const float c2v = __ldg(&g_c2[code]);

    for (int li = tg; li < nf; li += 4) {
        const int tok = g_list[li];
        xs[tid] = __ldg(x + (size_t)tok * DD + tid);
        __syncthreads();
        float p = 0.f;
        const float* xr = xs + q * 64;
        #pragma unroll
        for (int d = 0; d < 64; d++) p = fmaf(creg[d], xr[d], p);
        p += __shfl_xor_sync(0xffffffffu, p, 1);
        p += __shfl_xor_sync(0xffffffffu, p, 2);
        unsigned long long key = ~0ull;
        if (q == 0) {
            float s = c2v - 2.f * p + 4096.f;     // shift keeps s > 0 -> monotone bits
            key = ((unsigned long long)__float_as_uint(s) << 32) | (unsigned)code;
        }
        key = u64min(key, __shfl_xor_sync(0xffffffffu, key, 4));
        key = u64min(key, __shfl_xor_sync(0xffffffffu, key, 8));
        key = u64min(key, __shfl_xor_sync(0xffffffffu, key, 16));
        if ((tid & 31) == 0) wmin[tid >> 5] = key;
        __syncthreads();                           // wmin ready; also guards xs rewrite
        if (tid == 0) {
            unsigned long long k = wmin[0];
            #pragma unroll
            for (int w = 1; w < 8; w++) k = u64min(k, wmin[w]);
            atomicMin(&g_resc[tok], k);
        }
    }
}

// ---------------------------------------------------------------------------
// Kernel 4: outputs. Layout: [x_recon | z_e | z_q | indices(float)]
// ---------------------------------------------------------------------------
__global__ void scatter_kernel(const float* __restrict__ x,
                               const float* __restrict__ cb,
                               float* __restrict__ out) {
    const int t = blockIdx.x;
    const int d = threadIdx.x;
    const int idx = g_flag[t] ? (int)(unsigned)(g_resc[t] & 0xffffffffull) : g_idx[t];
    const float v  = __ldg(cb + (size_t)idx * DD + d);
    const float xe = __ldg(x  + (size_t)t   * DD + d);
    const size_t BND = (size_t)M_TOK * DD;
    out[(size_t)t * DD + d]           = v;
    out[BND + (size_t)t * DD + d]     = xe;
    out[2 * BND + (size_t)t * DD + d] = v;
    if (d == 0) out[3 * BND + t] = (float)idx;
}

// ---------------------------------------------------------------------------
extern "C" void kernel_launch(void* const* d_in, const int* in_sizes, int n_in,
                              void* d_out, int out_size) {
    const float* x  = (const float*)d_in[0];
    const float* cb = (const float*)d_in[1];
    float* out = (float*)d_out;

    cvt_cb_kernel<<<KK, DD>>>(cb);

    cudaFuncSetAttribute(vq_mma_kernel,
                         cudaFuncAttributeMaxDynamicSharedMemorySize, SMEM_TOTAL);
    vq_mma_kernel<<<M_TOK / M_TILE, THREADS, SMEM_TOTAL>>>(x);

    resc_kernel<<<512, 256>>>(x, cb);

    scatter_kernel<<<M_TOK, DD>>>(x, cb, out);
}

// round 14
// speedup vs baseline: 4.7311x; 2.0303x over previous
#include <cuda_runtime.h>
#include <cuda_fp16.h>

#define BB 8
#define NN 2048
#define DD 256
#define KK 8192
#define M_TOK (BB*NN)          // 16384

#define M_TILE 64
#define N_TILE 128
#define NT (KK / N_TILE)       // 64 n-tiles
#define NCHUNK (NT * 8)        // 512 chunks of 32 halves (8 per n-tile)
#define THREADS 256
#define EPS 0.25f

#define LDA 264                // A smem stride in halves (528 B, conflict-free ldmatrix)
#define LDB 40                 // B smem stride in halves (80 B)
#define B_STAGE 10240          // 128 * 80 (hi only)

// smem byte offsets
#define SM_AHI 0
#define SM_B   33792                    // 64*264*2 ; 2 stages x 10240
#define SMEM_TOTAL 54272

__device__ __align__(1024) __half g_cb_hi[KK*DD];
__device__ float g_c2[KK];
__device__ int   g_idx[M_TOK];
__device__ int   g_flag[M_TOK];
__device__ int   g_list[M_TOK];
__device__ int   g_nflag;
__device__ unsigned long long g_resc[M_TOK];

// ---- PTX helpers -----------------------------------------------------------
__device__ __forceinline__ void ldsm4(unsigned& r0, unsigned& r1, unsigned& r2,
                                      unsigned& r3, unsigned addr) {
    asm volatile("ldmatrix.sync.aligned.m8n8.x4.shared.b16 {%0,%1,%2,%3}, [%4];"
                 : "=r"(r0), "=r"(r1), "=r"(r2), "=r"(r3) : "r"(addr));
}
__device__ __forceinline__ void mma16816(float* c, unsigned a0, unsigned a1,
                                         unsigned a2, unsigned a3,
                                         unsigned b0, unsigned b1) {
    asm volatile("mma.sync.aligned.m16n8k16.row.col.f32.f16.f16.f32 "
                 "{%0,%1,%2,%3}, {%4,%5,%6,%7}, {%8,%9}, {%0,%1,%2,%3};"
                 : "+f"(c[0]), "+f"(c[1]), "+f"(c[2]), "+f"(c[3])
                 : "r"(a0), "r"(a1), "r"(a2), "r"(a3), "r"(b0), "r"(b1));
}
__device__ __forceinline__ void cp16(unsigned dst, const void* src) {
    asm volatile("cp.async.cg.shared.global [%0], [%1], 16;"
                 :: "r"(dst), "l"((unsigned long long)__cvta_generic_to_global(src))
                 : "memory");
}
#define CP_COMMIT() asm volatile("cp.async.commit_group;" ::: "memory")
#define CP_WAIT1()  asm volatile("cp.async.wait_group 1;" ::: "memory")

__device__ __forceinline__ unsigned long long u64min(unsigned long long a,
                                                     unsigned long long b) {
    return a < b ? a : b;
}

// ---------------------------------------------------------------------------
// Kernel 1: codebook fp16 hi split + squared norms. One block per code row.
// ---------------------------------------------------------------------------
__global__ void cvt_cb_kernel(const float* __restrict__ cb) {
    const int row = blockIdx.x, d = threadIdx.x;
    if (row == 0 && d == 0) g_nflag = 0;            // reset flag counter each launch
    float v = cb[row * DD + d];
    g_cb_hi[row * DD + d] = __float2half_rn(v);
    float s = v * v;
    #pragma unroll
    for (int o = 16; o; o >>= 1) s += __shfl_xor_sync(0xffffffffu, s, o);
    __shared__ float ws[8];
    if ((threadIdx.x & 31) == 0) ws[threadIdx.x >> 5] = s;
    __syncthreads();
    if (threadIdx.x == 0) {
        float t = 0.f;
        #pragma unroll
        for (int w = 0; w < 8; w++) t += ws[w];
        g_c2[row] = t;
    }
}

// ---------------------------------------------------------------------------
// Kernel 2: single-pass fp16-hi HMMA + top-3 tracking + inline exact tie-break
// ---------------------------------------------------------------------------
__global__ void __launch_bounds__(THREADS, 2)
vq_mma_kernel(const float* __restrict__ x, const float* __restrict__ cb) {
    extern __shared__ char smem[];
    const unsigned sb = (unsigned)__cvta_generic_to_shared(smem);
    const int tid  = threadIdx.x;
    const int wid  = tid >> 5;
    const int lane = tid & 31;
    const int wm   = wid >> 2;          // 0..1  (32 rows each)
    const int wn   = wid & 3;           // 0..3  (32 cols each)
    const int rowBase = blockIdx.x * M_TILE;

    // ---- load A tile: 64 tokens x 256 d, fp32 -> fp16 hi in padded smem
    for (int r = 0; r < 16; r++) {
        int i   = r * THREADS + tid;         // float4 index, 4096 total
        int tok = i >> 6, dg = i & 63;
        float4 v = __ldg((const float4*)(x + (size_t)(rowBase + tok) * DD + dg * 4));
        unsigned off = (unsigned)(tok * LDA + dg * 4) * 2;
        *(__half2*)(smem + SM_AHI + off)     = __halves2half2(__float2half_rn(v.x),
                                                              __float2half_rn(v.y));
        *(__half2*)(smem + SM_AHI + off + 4) = __halves2half2(__float2half_rn(v.z),
                                                              __float2half_rn(v.w));
    }
    __syncthreads();

    // per-thread ldmatrix base offsets
    const unsigned aoff = ((unsigned)((wm * 32 + (lane & 15)) * LDA) + (lane >> 4) * 8) * 2;
    const unsigned boff = ((unsigned)((wn * 32 + (lane >> 4) * 8 + (lane & 7)) * LDB)
                           + ((lane >> 3) & 1) * 8) * 2;

    float acc[2][4][4];
    #pragma unroll
    for (int mi = 0; mi < 2; mi++)
        #pragma unroll
        for (int ni = 0; ni < 4; ni++)
            #pragma unroll
            for (int q = 0; q < 4; q++) acc[mi][ni][q] = 0.f;

    float b1[2][2], b2[2][2], b3[2][2];
    int   i1[2][2], i2[2][2];
    #pragma unroll
    for (int mi = 0; mi < 2; mi++)
        #pragma unroll
        for (int rr = 0; rr < 2; rr++) {
            b1[mi][rr] = 3.4e38f; b2[mi][rr] = 3.4e38f; b3[mi][rr] = 3.4e38f;
            i1[mi][rr] = 0; i2[mi][rr] = 0;
        }

    // prefetch chunk 0 into stage 0  (chunk = 128 codes x 32 halves, hi only)
    #pragma unroll
    for (int rep = 0; rep < 2; rep++) {
        int idx = rep * THREADS + tid;               // 512 x 16B
        int r = idx >> 2, cc = idx & 3;
        cp16(sb + SM_B + r * (LDB * 2) + cc * 16,
             g_cb_hi + ((size_t)r * DD + cc * 8));
    }
    CP_COMMIT();

    for (int g = 0; g < NCHUNK; g++) {
        // prefetch chunk g+1 into stage (g+1)&1
        if (g + 1 < NCHUNK) {
            const int nt = (g + 1) >> 3, kc = (g + 1) & 7, st = (g + 1) & 1;
            #pragma unroll
            for (int rep = 0; rep < 2; rep++) {
                int idx = rep * THREADS + tid;
                int r = idx >> 2, cc = idx & 3;
                cp16(sb + SM_B + st * B_STAGE + r * (LDB * 2) + cc * 16,
                     g_cb_hi + ((size_t)(nt * N_TILE + r) * DD + kc * 32 + cc * 8));
            }
        }
        CP_COMMIT();
        CP_WAIT1();
        __syncthreads();

        const unsigned bbase = sb + SM_B + (unsigned)(g & 1) * B_STAGE;
        const unsigned kb2 = (unsigned)((g & 7) * 32) * 2;    // A k-chunk byte offset

        #pragma unroll
        for (int k16 = 0; k16 < 2; k16++) {
            const unsigned kaA = kb2 + (unsigned)k16 * 32;    // A: full-K resident
            const unsigned kaB = (unsigned)k16 * 32;          // B: stage chunk-relative
            unsigned ah[2][4], bh[2][4];
            #pragma unroll
            for (int mi = 0; mi < 2; mi++)
                ldsm4(ah[mi][0], ah[mi][1], ah[mi][2], ah[mi][3],
                      sb + SM_AHI + aoff + (unsigned)(mi * 16 * LDA * 2) + kaA);
            #pragma unroll
            for (int p = 0; p < 2; p++)
                ldsm4(bh[p][0], bh[p][1], bh[p][2], bh[p][3],
                      bbase + boff + (unsigned)(p * 16 * LDB * 2) + kaB);
            #pragma unroll
            for (int mi = 0; mi < 2; mi++)
                #pragma unroll
                for (int ni = 0; ni < 4; ni++)
                    mma16816(acc[mi][ni], ah[mi][0], ah[mi][1], ah[mi][2], ah[mi][3],
                             bh[ni >> 1][(ni & 1) * 2], bh[ni >> 1][(ni & 1) * 2 + 1]);
        }

        if ((g & 7) == 7) {
            // drain: s = c2 - 2*cross, track top-3; zero accumulators
            const int nt = g >> 3;
            #pragma unroll
            for (int ni = 0; ni < 4; ni++) {
                int col = nt * N_TILE + wn * 32 + ni * 8 + (lane & 3) * 2;
                float c20 = __ldg(&g_c2[col]);
                float c21 = __ldg(&g_c2[col + 1]);
                #pragma unroll
                for (int mi = 0; mi < 2; mi++) {
                    #pragma unroll
                    for (int rr = 0; rr < 2; rr++) {
                        #pragma unroll
                        for (int e = 0; e < 2; e++) {
                            float s = fmaf(-2.0f, acc[mi][ni][rr * 2 + e], e ? c21 : c20);
                            int   c = col + e;
                            if (s < b1[mi][rr]) {
                                b3[mi][rr] = b2[mi][rr];
                                b2[mi][rr] = b1[mi][rr]; i2[mi][rr] = i1[mi][rr];
                                b1[mi][rr] = s;          i1[mi][rr] = c;
                            } else if (s < b2[mi][rr]) {
                                b3[mi][rr] = b2[mi][rr];
                                b2[mi][rr] = s;          i2[mi][rr] = c;
                            } else if (s < b3[mi][rr]) {
                                b3[mi][rr] = s;
                            }
                            acc[mi][ni][rr * 2 + e] = 0.f;
                        }
                    }
                }
            }
        }
        __syncthreads();   // protect stage g&1 before next prefetch overwrites it
    }

    // ---- cross-thread top-3 merge (16 candidates per row), reuse B region
    float* rv1 = (float*)(smem + SM_B);             // [64][16]
    int*   ri1 = (int*)  (smem + SM_B + 4096);
    float* rv2 = (float*)(smem + SM_B + 8192);
    int*   ri2 = (int*)  (smem + SM_B + 12288);
    float* rv3 = (float*)(smem + SM_B + 16384);
    const int cand = wn * 4 + (lane & 3);
    #pragma unroll
    for (int mi = 0; mi < 2; mi++)
        #pragma unroll
        for (int rr = 0; rr < 2; rr++) {
            int row = wm * 32 + mi * 16 + rr * 8 + (lane >> 2);
            rv1[row * 16 + cand] = b1[mi][rr];
            ri1[row * 16 + cand] = i1[mi][rr];
            rv2[row * 16 + cand] = b2[mi][rr];
            ri2[row * 16 + cand] = i2[mi][rr];
            rv3[row * 16 + cand] = b3[mi][rr];
        }
    __syncthreads();
    if (tid < M_TILE) {
        float B1 = 3.4e38f, B2 = 3.4e38f, B3 = 3.4e38f;
        int   I1 = 0, I2 = 0;
        #pragma unroll
        for (int t = 0; t < 16; t++) {
            #pragma unroll
            for (int s3 = 0; s3 < 3; s3++) {
                float v; int j;
                if (s3 == 0)      { v = rv1[tid * 16 + t]; j = ri1[tid * 16 + t]; }
                else if (s3 == 1) { v = rv2[tid * 16 + t]; j = ri2[tid * 16 + t]; }
                else              { v = rv3[tid * 16 + t]; j = 0x7FFFFFFF; }
                if (v < B1 || (v == B1 && j < I1)) {
                    B3 = B2; B2 = B1; I2 = I1; B1 = v; I1 = j;
                } else if (v < B2 || (v == B2 && j < I2)) {
                    B3 = B2; B2 = v; I2 = j;
                } else if (v < B3) B3 = v;
            }
        }
        const int tok = rowBase + tid;
        int fl = 0;
        int bi = I1;
        if (B3 - B1 < EPS) {
            // deep (3-way) near-tie: full exact rescore needed (rare)
            fl = 1;
            g_resc[tok] = ~0ull;
            int p = atomicAdd(&g_nflag, 1);
            g_list[p] = tok;
        } else if (B2 - B1 < EPS) {
            // 2-way near-tie: exact fp32 compare of I1 vs I2 inline
            const float4* xr = (const float4*)(x  + (size_t)tok * DD);
            const float4* p1 = (const float4*)(cb + (size_t)I1  * DD);
            const float4* p2 = (const float4*)(cb + (size_t)I2  * DD);
            float d1 = 0.f, d2 = 0.f;
            #pragma unroll 8
            for (int d4 = 0; d4 < 64; d4++) {
                float4 xv = __ldg(xr + d4);
                float4 a  = __ldg(p1 + d4);
                float4 b  = __ldg(p2 + d4);
                d1 += xv.x * a.x + xv.y * a.y + xv.z * a.z + xv.w * a.w;
                d2 += xv.x * b.x + xv.y * b.y + xv.z * b.z + xv.w * b.w;
            }
            float e1 = __ldg(&g_c2[I1]) - 2.f * d1;
            float e2 = __ldg(&g_c2[I2]) - 2.f * d2;
            bi = (e2 < e1 || (e2 == e1 && I2 < I1)) ? I2 : I1;
        }
        g_flag[tok] = fl;
        g_idx[tok]  = bi;
    }
}

// ---------------------------------------------------------------------------
// Kernel 3: exact fp32 rescore of deep-tie tokens (expected ~0-10 tokens).
//   grid = 512: 128 code tiles (64 codes) x 4 token groups; code tile in regs.
// ---------------------------------------------------------------------------
__global__ void __launch_bounds__(256, 2)
resc_kernel(const float* __restrict__ x, const float* __restrict__ cb) {
    __shared__ float xs[4 * 68];                    // padded: q*68+d, conflict-free
    __shared__ unsigned long long wmin[8];
    const int tid = threadIdx.x;
    const int ct  = blockIdx.x & 127;     // code tile: 64 codes
    const int tg  = blockIdx.x >> 7;      // 0..3
    const int j = tid >> 2, q = tid & 3;
    const int code = ct * 64 + j;

    const int nf = g_nflag;
    if (nf == 0) return;

    float creg[64];
    {
        const float4* csrc = (const float4*)(cb + (size_t)code * DD + q * 64);
        #pragma unroll
        for (int d4 = 0; d4 < 16; d4++) {
            float4 v = __ldg(csrc + d4);
            creg[d4 * 4]     = v.x; creg[d4 * 4 + 1] = v.y;
            creg[d4 * 4 + 2] = v.z; creg[d4 * 4 + 3] = v.w;
        }
    }
    const float c2v = __ldg(&g_c2[code]);

    for (int li = tg; li < nf; li += 4) {
        const int tok = g_list[li];
        xs[(tid >> 6) * 68 + (tid & 63)] = __ldg(x + (size_t)tok * DD + tid);
        __syncthreads();
        float p = 0.f;
        const float* xr = xs + q * 68;
        #pragma unroll
        for (int d = 0; d < 64; d++) p = fmaf(creg[d], xr[d], p);
        p += __shfl_xor_sync(0xffffffffu, p, 1);
        p += __shfl_xor_sync(0xffffffffu, p, 2);
        unsigned long long key = ~0ull;
        if (q == 0) {
            float s = c2v - 2.f * p + 4096.f;     // shift keeps s > 0 -> monotone bits
            key = ((unsigned long long)__float_as_uint(s) << 32) | (unsigned)code;
        }
        key = u64min(key, __shfl_xor_sync(0xffffffffu, key, 4));
        key = u64min(key, __shfl_xor_sync(0xffffffffu, key, 8));
        key = u64min(key, __shfl_xor_sync(0xffffffffu, key, 16));
        if ((tid & 31) == 0) wmin[tid >> 5] = key;
        __syncthreads();                           // wmin ready; also guards xs rewrite
        if (tid == 0) {
            unsigned long long k = wmin[0];
            #pragma unroll
            for (int w = 1; w < 8; w++) k = u64min(k, wmin[w]);
            atomicMin(&g_resc[tok], k);
        }
    }
}

// ---------------------------------------------------------------------------
// Kernel 4: outputs. Layout: [x_recon | z_e | z_q | indices(float)]
// ---------------------------------------------------------------------------
__global__ void scatter_kernel(const float* __restrict__ x,
                               const float* __restrict__ cb,
                               float* __restrict__ out) {
    const int t = blockIdx.x;
    const int d = threadIdx.x;
    const int idx = g_flag[t] ? (int)(unsigned)(g_resc[t] & 0xffffffffull) : g_idx[t];
    const float v  = __ldg(cb + (size_t)idx * DD + d);
    const float xe = __ldg(x  + (size_t)t   * DD + d);
    const size_t BND = (size_t)M_TOK * DD;
    out[(size_t)t * DD + d]           = v;
    out[BND + (size_t)t * DD + d]     = xe;
    out[2 * BND + (size_t)t * DD + d] = v;
    if (d == 0) out[3 * BND + t] = (float)idx;
}

// ---------------------------------------------------------------------------
extern "C" void kernel_launch(void* const* d_in, const int* in_sizes, int n_in,
                              void* d_out, int out_size) {
    const float* x  = (const float*)d_in[0];
    const float* cb = (const float*)d_in[1];
    float* out = (float*)d_out;

    cvt_cb_kernel<<<KK, DD>>>(cb);

    cudaFuncSetAttribute(vq_mma_kernel,
                         cudaFuncAttributeMaxDynamicSharedMemorySize, SMEM_TOTAL);
    vq_mma_kernel<<<M_TOK / M_TILE, THREADS, SMEM_TOTAL>>>(x, cb);

    resc_kernel<<<512, 256>>>(x, cb);

    scatter_kernel<<<M_TOK, DD>>>(x, cb, out);
}

// round 16
// speedup vs baseline: 5.3102x; 1.1224x over previous
#include <cuda_runtime.h>
#include <cuda_fp16.h>

#define BB 8
#define NN 2048
#define DD 256
#define KK 8192
#define M_TOK (BB*NN)          // 16384

#define M_TILE 64
#define N_TILE 128
#define NT (KK / N_TILE)       // 64 n-tiles
#define NCHUNK (NT * 4)        // 256 chunks of 64 halves (4 per n-tile)
#define THREADS 256
#define EPS 0.25f

#define LDA 264                // A smem stride in halves (528 B, conflict-free ldmatrix)
#define LDB_BYTES 144          // B row stride: 128 B data + 16 B pad (conflict-free)
#define B_STAGE 18432          // 128 * 144
#define NSTAGE 3

// smem byte offsets (per-CTA total 89088 -> 2 CTAs/SM)
#define SM_AHI 0
#define SM_B   33792                    // 64*264*2 ; 3 stages x 18432
#define SMEM_TOTAL (SM_B + NSTAGE * B_STAGE)

__device__ __align__(1024) __half g_cb_hi[KK*DD];
__device__ float g_c2[KK];
__device__ int   g_idx[M_TOK];
__device__ int   g_flag[M_TOK];
__device__ int   g_list[M_TOK];
__device__ int   g_nflag;
__device__ unsigned long long g_resc[M_TOK];

// ---- PTX helpers -----------------------------------------------------------
__device__ __forceinline__ void ldsm4(unsigned& r0, unsigned& r1, unsigned& r2,
                                      unsigned& r3, unsigned addr) {
    asm volatile("ldmatrix.sync.aligned.m8n8.x4.shared.b16 {%0,%1,%2,%3}, [%4];"
                 : "=r"(r0), "=r"(r1), "=r"(r2), "=r"(r3) : "r"(addr));
}
__device__ __forceinline__ void mma16816(float* c, unsigned a0, unsigned a1,
                                         unsigned a2, unsigned a3,
                                         unsigned b0, unsigned b1) {
    asm volatile("mma.sync.aligned.m16n8k16.row.col.f32.f16.f16.f32 "
                 "{%0,%1,%2,%3}, {%4,%5,%6,%7}, {%8,%9}, {%0,%1,%2,%3};"
                 : "+f"(c[0]), "+f"(c[1]), "+f"(c[2]), "+f"(c[3])
                 : "r"(a0), "r"(a1), "r"(a2), "r"(a3), "r"(b0), "r"(b1));
}
__device__ __forceinline__ void cp16(unsigned dst, const void* src) {
    asm volatile("cp.async.cg.shared.global [%0], [%1], 16;"
                 :: "r"(dst), "l"((unsigned long long)__cvta_generic_to_global(src))
                 : "memory");
}
#define CP_COMMIT() asm volatile("cp.async.commit_group;" ::: "memory")
#define CP_WAIT1()  asm volatile("cp.async.wait_group 1;" ::: "memory")

__device__ __forceinline__ unsigned long long u64min(unsigned long long a,
                                                     unsigned long long b) {
    return a < b ? a : b;
}

// ---------------------------------------------------------------------------
// Kernel 1: codebook fp16 hi split + squared norms. One block per code row.
// ---------------------------------------------------------------------------
__global__ void cvt_cb_kernel(const float* __restrict__ cb) {
    const int row = blockIdx.x, d = threadIdx.x;
    if (row == 0 && d == 0) g_nflag = 0;            // reset flag counter each launch
    float v = cb[row * DD + d];
    g_cb_hi[row * DD + d] = __float2half_rn(v);
    float s = v * v;
    #pragma unroll
    for (int o = 16; o; o >>= 1) s += __shfl_xor_sync(0xffffffffu, s, o);
    __shared__ float ws[8];
    if ((threadIdx.x & 31) == 0) ws[threadIdx.x >> 5] = s;
    __syncthreads();
    if (threadIdx.x == 0) {
        float t = 0.f;
        #pragma unroll
        for (int w = 0; w < 8; w++) t += ws[w];
        g_c2[row] = t;
    }
}

// ---------------------------------------------------------------------------
// chunk prefetch: chunk c = (n-tile c>>2, k-chunk c&3) -> stage c%3
// ---------------------------------------------------------------------------
__device__ __forceinline__ void prefetch_chunk(unsigned sb, int c, int tid) {
    const int nt = c >> 2, kc = c & 3, st = c % NSTAGE;
    #pragma unroll
    for (int rep = 0; rep < 4; rep++) {
        int idx = rep * THREADS + tid;               // 1024 x 16B
        int r = idx >> 3, cc = idx & 7;
        cp16(sb + SM_B + st * B_STAGE + r * LDB_BYTES + cc * 16,
             g_cb_hi + ((size_t)(nt * N_TILE + r) * DD + kc * 64 + cc * 8));
    }
}

// ---------------------------------------------------------------------------
// Kernel 2: single-pass fp16-hi HMMA + top-3 tracking + inline exact tie-break
//   3-stage pipeline, ONE __syncthreads per chunk, KC=64.
// ---------------------------------------------------------------------------
__global__ void __launch_bounds__(THREADS, 2)
vq_mma_kernel(const float* __restrict__ x, const float* __restrict__ cb) {
    extern __shared__ char smem[];
    const unsigned sb = (unsigned)__cvta_generic_to_shared(smem);
    const int tid  = threadIdx.x;
    const int wid  = tid >> 5;
    const int lane = tid & 31;
    const int wm   = wid >> 2;          // 0..1  (32 rows each)
    const int wn   = wid & 3;           // 0..3  (32 cols each)
    const int rowBase = blockIdx.x * M_TILE;

    // ---- load A tile: 64 tokens x 256 d, fp32 -> fp16 hi in padded smem
    for (int r = 0; r < 16; r++) {
        int i   = r * THREADS + tid;         // float4 index, 4096 total
        int tok = i >> 6, dg = i & 63;
        float4 v = __ldg((const float4*)(x + (size_t)(rowBase + tok) * DD + dg * 4));
        unsigned off = (unsigned)(tok * LDA + dg * 4) * 2;
        *(__half2*)(smem + SM_AHI + off)     = __halves2half2(__float2half_rn(v.x),
                                                              __float2half_rn(v.y));
        *(__half2*)(smem + SM_AHI + off + 4) = __halves2half2(__float2half_rn(v.z),
                                                              __float2half_rn(v.w));
    }

    // per-thread ldmatrix base offsets
    const unsigned aoff = ((unsigned)((wm * 32 + (lane & 15)) * LDA) + (lane >> 4) * 8) * 2;
    const unsigned boff = (unsigned)(wn * 32 + (lane >> 4) * 8 + (lane & 7)) * LDB_BYTES
                        + (unsigned)((lane >> 3) & 1) * 16;

    float acc[2][4][4];
    #pragma unroll
    for (int mi = 0; mi < 2; mi++)
        #pragma unroll
        for (int ni = 0; ni < 4; ni++)
            #pragma unroll
            for (int q = 0; q < 4; q++) acc[mi][ni][q] = 0.f;

    float b1[2][2], b2[2][2], b3[2][2];
    int   i1[2][2], i2[2][2];
    #pragma unroll
    for (int mi = 0; mi < 2; mi++)
        #pragma unroll
        for (int rr = 0; rr < 2; rr++) {
            b1[mi][rr] = 3.4e38f; b2[mi][rr] = 3.4e38f; b3[mi][rr] = 3.4e38f;
            i1[mi][rr] = 0; i2[mi][rr] = 0;
        }

    // prologue: prefetch chunks 0 and 1
    prefetch_chunk(sb, 0, tid);
    CP_COMMIT();
    prefetch_chunk(sb, 1, tid);
    CP_COMMIT();
    __syncthreads();                    // A tile visible to all warps

    for (int g = 0; g < NCHUNK; g++) {
        CP_WAIT1();                     // chunk g's data landed (g+1 may be in flight)
        __syncthreads();                // all warps: g's data visible; stage (g-1)%3 free

        // prefetch g+2 into stage (g+2)%3 == (g-1)%3 (consumed last iteration)
        if (g + 2 < NCHUNK) prefetch_chunk(sb, g + 2, tid);
        CP_COMMIT();                    // commit every iter to keep group accounting

        const unsigned bbase = sb + SM_B + (unsigned)(g % NSTAGE) * B_STAGE;
        const unsigned kb2 = (unsigned)(g & 3) * 128;         // A k-chunk byte offset

        #pragma unroll
        for (int k16 = 0; k16 < 4; k16++) {
            const unsigned kaA = kb2 + (unsigned)k16 * 32;    // A: full-K resident
            const unsigned kaB = (unsigned)k16 * 32;          // B: stage chunk-relative
            unsigned ah[2][4], bh[2][4];
            #pragma unroll
            for (int mi = 0; mi < 2; mi++)
                ldsm4(ah[mi][0], ah[mi][1], ah[mi][2], ah[mi][3],
                      sb + SM_AHI + aoff + (unsigned)(mi * 16 * LDA * 2) + kaA);
            #pragma unroll
            for (int p = 0; p < 2; p++)
                ldsm4(bh[p][0], bh[p][1], bh[p][2], bh[p][3],
                      bbase + boff + (unsigned)(p * 16 * LDB_BYTES) + kaB);
            #pragma unroll
            for (int mi = 0; mi < 2; mi++)
                #pragma unroll
                for (int ni = 0; ni < 4; ni++)
                    mma16816(acc[mi][ni], ah[mi][0], ah[mi][1], ah[mi][2], ah[mi][3],
                             bh[ni >> 1][(ni & 1) * 2], bh[ni >> 1][(ni & 1) * 2 + 1]);
        }

        if ((g & 3) == 3) {
            // drain: s = c2 - 2*cross, track top-3; zero accumulators
            const int nt = g >> 2;
            #pragma unroll
            for (int ni = 0; ni < 4; ni++) {
                int col = nt * N_TILE + wn * 32 + ni * 8 + (lane & 3) * 2;
                float c20 = __ldg(&g_c2[col]);
                float c21 = __ldg(&g_c2[col + 1]);
                #pragma unroll
                for (int mi = 0; mi < 2; mi++) {
                    #pragma unroll
                    for (int rr = 0; rr < 2; rr++) {
                        #pragma unroll
                        for (int e = 0; e < 2; e++) {
                            float s = fmaf(-2.0f, acc[mi][ni][rr * 2 + e], e ? c21 : c20);
                            int   c = col + e;
                            if (s < b1[mi][rr]) {
                                b3[mi][rr] = b2[mi][rr];
                                b2[mi][rr] = b1[mi][rr]; i2[mi][rr] = i1[mi][rr];
                                b1[mi][rr] = s;          i1[mi][rr] = c;
                            } else if (s < b2[mi][rr]) {
                                b3[mi][rr] = b2[mi][rr];
                                b2[mi][rr] = s;          i2[mi][rr] = c;
                            } else if (s < b3[mi][rr]) {
                                b3[mi][rr] = s;
                            }
                            acc[mi][ni][rr * 2 + e] = 0.f;
                        }
                    }
                }
            }
        }
    }

    // ---- cross-thread top-3 merge (16 candidates per row), reuse B region
    __syncthreads();
    float* rv1 = (float*)(smem + SM_B);             // [64][16]
    int*   ri1 = (int*)  (smem + SM_B + 4096);
    float* rv2 = (float*)(smem + SM_B + 8192);
    int*   ri2 = (int*)  (smem + SM_B + 12288);
    float* rv3 = (float*)(smem + SM_B + 16384);
    const int cand = wn * 4 + (lane & 3);
    #pragma unroll
    for (int mi = 0; mi < 2; mi++)
        #pragma unroll
        for (int rr = 0; rr < 2; rr++) {
            int row = wm * 32 + mi * 16 + rr * 8 + (lane >> 2);
            rv1[row * 16 + cand] = b1[mi][rr];
            ri1[row * 16 + cand] = i1[mi][rr];
            rv2[row * 16 + cand] = b2[mi][rr];
            ri2[row * 16 + cand] = i2[mi][rr];
            rv3[row * 16 + cand] = b3[mi][rr];
        }
    __syncthreads();
    if (tid < M_TILE) {
        float B1 = 3.4e38f, B2 = 3.4e38f, B3 = 3.4e38f;
        int   I1 = 0, I2 = 0;
        #pragma unroll
        for (int t = 0; t < 16; t++) {
            #pragma unroll
            for (int s3 = 0; s3 < 3; s3++) {
                float v; int j;
                if (s3 == 0)      { v = rv1[tid * 16 + t]; j = ri1[tid * 16 + t]; }
                else if (s3 == 1) { v = rv2[tid * 16 + t]; j = ri2[tid * 16 + t]; }
                else              { v = rv3[tid * 16 + t]; j = 0x7FFFFFFF; }
                if (v < B1 || (v == B1 && j < I1)) {
                    B3 = B2; B2 = B1; I2 = I1; B1 = v; I1 = j;
                } else if (v < B2 || (v == B2 && j < I2)) {
                    B3 = B2; B2 = v; I2 = j;
                } else if (v < B3) B3 = v;
            }
        }
        const int tok = rowBase + tid;
        int fl = 0;
        int bi = I1;
        if (B3 - B1 < EPS) {
            // deep (3-way) near-tie: full exact rescore needed (rare)
            fl = 1;
            g_resc[tok] = ~0ull;
            int p = atomicAdd(&g_nflag, 1);
            g_list[p] = tok;
        } else if (B2 - B1 < EPS) {
            // 2-way near-tie: exact fp32 compare of I1 vs I2 inline
            const float4* xr = (const float4*)(x  + (size_t)tok * DD);
            const float4* p1 = (const float4*)(cb + (size_t)I1  * DD);
            const float4* p2 = (const float4*)(cb + (size_t)I2  * DD);
            float d1 = 0.f, d2 = 0.f;
            #pragma unroll 8
            for (int d4 = 0; d4 < 64; d4++) {
                float4 xv = __ldg(xr + d4);
                float4 a  = __ldg(p1 + d4);
                float4 b  = __ldg(p2 + d4);
                d1 += xv.x * a.x + xv.y * a.y + xv.z * a.z + xv.w * a.w;
                d2 += xv.x * b.x + xv.y * b.y + xv.z * b.z + xv.w * b.w;
            }
            float e1 = __ldg(&g_c2[I1]) - 2.f * d1;
            float e2 = __ldg(&g_c2[I2]) - 2.f * d2;
            bi = (e2 < e1 || (e2 == e1 && I2 < I1)) ? I2 : I1;
        }
        g_flag[tok] = fl;
        g_idx[tok]  = bi;
    }
}

// ---------------------------------------------------------------------------
// Kernel 3: exact fp32 rescore of deep-tie tokens (expected ~0-10 tokens).
//   grid = 512: 128 code tiles (64 codes) x 4 token groups; code tile in regs.
// ---------------------------------------------------------------------------
__global__ void __launch_bounds__(256, 2)
resc_kernel(const float* __restrict__ x, const float* __restrict__ cb) {
    __shared__ float xs[4 * 68];                    // padded: q*68+d, conflict-free
    __shared__ unsigned long long wmin[8];
    const int tid = threadIdx.x;
    const int ct  = blockIdx.x & 127;     // code tile: 64 codes
    const int tg  = blockIdx.x >> 7;      // 0..3
    const int j = tid >> 2, q = tid & 3;
    const int code = ct * 64 + j;

    const int nf = g_nflag;
    if (nf == 0) return;

    float creg[64];
    {
        const float4* csrc = (const float4*)(cb + (size_t)code * DD + q * 64);
        #pragma unroll
        for (int d4 = 0; d4 < 16; d4++) {
            float4 v = __ldg(csrc + d4);
            creg[d4 * 4]     = v.x; creg[d4 * 4 + 1] = v.y;
            creg[d4 * 4 + 2] = v.z; creg[d4 * 4 + 3] = v.w;
        }
    }
    const float c2v = __ldg(&g_c2[code]);

    for (int li = tg; li < nf; li += 4) {
        const int tok = g_list[li];
        xs[(tid >> 6) * 68 + (tid & 63)] = __ldg(x + (size_t)tok * DD + tid);
        __syncthreads();
        float p = 0.f;
        const float* xr = xs + q * 68;
        #pragma unroll
        for (int d = 0; d < 64; d++) p = fmaf(creg[d], xr[d], p);
        p += __shfl_xor_sync(0xffffffffu, p, 1);
        p += __shfl_xor_sync(0xffffffffu, p, 2);
        unsigned long long key = ~0ull;
        if (q == 0) {
            float s = c2v - 2.f * p + 4096.f;     // shift keeps s > 0 -> monotone bits
            key = ((unsigned long long)__float_as_uint(s) << 32) | (unsigned)code;
        }
        key = u64min(key, __shfl_xor_sync(0xffffffffu, key, 4));
        key = u64min(key, __shfl_xor_sync(0xffffffffu, key, 8));
        key = u64min(key, __shfl_xor_sync(0xffffffffu, key, 16));
        if ((tid & 31) == 0) wmin[tid >> 5] = key;
        __syncthreads();                           // wmin ready; also guards xs rewrite
        if (tid == 0) {
            unsigned long long k = wmin[0];
            #pragma unroll
            for (int w = 1; w < 8; w++) k = u64min(k, wmin[w]);
            atomicMin(&g_resc[tok], k);
        }
    }
}

// ---------------------------------------------------------------------------
// Kernel 4: outputs. Layout: [x_recon | z_e | z_q | indices(float)]
// ---------------------------------------------------------------------------
__global__ void scatter_kernel(const float* __restrict__ x,
                               const float* __restrict__ cb,
                               float* __restrict__ out) {
    const int t = blockIdx.x;
    const int d = threadIdx.x;
    const int idx = g_flag[t] ? (int)(unsigned)(g_resc[t] & 0xffffffffull) : g_idx[t];
    const float v  = __ldg(cb + (size_t)idx * DD + d);
    const float xe = __ldg(x  + (size_t)t   * DD + d);
    const size_t BND = (size_t)M_TOK * DD;
    out[(size_t)t * DD + d]           = v;
    out[BND + (size_t)t * DD + d]     = xe;
    out[2 * BND + (size_t)t * DD + d] = v;
    if (d == 0) out[3 * BND + t] = (float)idx;
}

// ---------------------------------------------------------------------------
extern "C" void kernel_launch(void* const* d_in, const int* in_sizes, int n_in,
                              void* d_out, int out_size) {
    const float* x  = (const float*)d_in[0];
    const float* cb = (const float*)d_in[1];
    float* out = (float*)d_out;

    cvt_cb_kernel<<<KK, DD>>>(cb);

    cudaFuncSetAttribute(vq_mma_kernel,
                         cudaFuncAttributeMaxDynamicSharedMemorySize, SMEM_TOTAL);
    vq_mma_kernel<<<M_TOK / M_TILE, THREADS, SMEM_TOTAL>>>(x, cb);

    resc_kernel<<<512, 256>>>(x, cb);

    scatter_kernel<<<M_TOK, DD>>>(x, cb, out);
}